// round 4
// baseline (speedup 1.0000x reference)
#include <cuda_runtime.h>

// ============================================================================
// GCNConv: out = sigmoid( scatter_add( (x@W)[row] * norm, col ) + b )
// norm = dis[row] * w * dis[col],  dis = rsqrt(deg),  deg = seg_sum(w, col) + 1
// Self loops (w=1) folded into GEMM epilogue: out_init[i] = h[i] * dis[i]^2.
//
// Inputs (metadata order): x[100000,128] f32, edge_index[2,E] (int32 or int64),
//                          edge_weight[E] f32, W[128,64] f32, b[64] f32
// Output: [100000,64] f32
// ============================================================================

#define NMAX 100000

// Static device scratch (no allocations allowed in kernel_launch).
__device__ float g_deg[NMAX];
__device__ float g_dis[NMAX];
__device__ float g_h[(size_t)NMAX * 64];
__device__ int   g_is64;

// ---------------------------------------------------------------------------
// Detect edge_index dtype. int64 little-endian with values < 2^31 has every
// odd 32-bit word == 0; int32 random indices in [0,100000) make 256
// consecutive odd words all-zero impossible in practice.
__global__ void k_detect(const int* __restrict__ ei32, int E) {
    __shared__ int nz;
    if (threadIdx.x == 0) nz = 0;
    __syncthreads();
    int idx = 2 * threadIdx.x + 1;           // odd words of first 256 pairs
    if (idx < 2 * E && ei32[idx] != 0) atomicOr(&nz, 1);
    __syncthreads();
    if (threadIdx.x == 0) g_is64 = (nz == 0) ? 1 : 0;
}

__device__ __forceinline__ int load_idx(const void* ei, int is64, size_t pos) {
    if (is64) return (int)((const long long*)ei)[pos];
    return ((const int*)ei)[pos];
}

// ---------------------------------------------------------------------------
// deg init: self-loop weight 1.0
__global__ void k_deg_init(int n) {
    int i = blockIdx.x * blockDim.x + threadIdx.x;
    if (i < n) g_deg[i] = 1.0f;
}

// deg accumulate: deg[col] += w
__global__ void k_deg_acc(const void* __restrict__ ei,
                          const float* __restrict__ ew, int E, int n) {
    int e = blockIdx.x * blockDim.x + threadIdx.x;
    if (e < E) {
        int is64 = g_is64;
        int c = load_idx(ei, is64, (size_t)E + e);
        if ((unsigned)c < (unsigned)n) atomicAdd(&g_deg[c], __ldg(&ew[e]));
    }
}

// dis = rsqrt(deg) (deg >= 1 always, guard kept for parity with reference)
__global__ void k_dis(int n) {
    int i = blockIdx.x * blockDim.x + threadIdx.x;
    if (i < n) {
        float d = g_deg[i];
        g_dis[i] = (d > 0.0f) ? rsqrtf(d) : 0.0f;
    }
}

// ---------------------------------------------------------------------------
// GEMM: h = x @ W  (M=100000, K=128, N=64), packed f32x2 FMA, W in smem.
// Epilogue: g_h[row] = h ; out[row] = h * dis[row]^2   (self-loop term)
__global__ void __launch_bounds__(256) k_gemm(const float* __restrict__ x,
                                              const float* __restrict__ W,
                                              float* __restrict__ out, int n) {
    // W is [128][64] row-major -> consecutive column pairs are contiguous:
    // reinterpret directly as 128*32 packed f32x2 (8B each) = 32 KB smem.
    __shared__ unsigned long long w2[128 * 32];
    const unsigned long long* Wp = (const unsigned long long*)W;
    for (int i = threadIdx.x; i < 128 * 32; i += blockDim.x) w2[i] = Wp[i];
    __syncthreads();

    int row = blockIdx.x * blockDim.x + threadIdx.x;
    if (row >= n) return;

    unsigned long long acc[32];
#pragma unroll
    for (int c = 0; c < 32; c++) acc[c] = 0ull;

    const float4* xr = (const float4*)(x + (size_t)row * 128);
#pragma unroll 2
    for (int k4 = 0; k4 < 32; k4++) {
        float4 xv = xr[k4];
        float xs[4] = {xv.x, xv.y, xv.z, xv.w};
#pragma unroll
        for (int j = 0; j < 4; j++) {
            unsigned long long xx;
            asm("mov.b64 %0, {%1, %1};" : "=l"(xx) : "f"(xs[j]));
            const unsigned long long* wr = &w2[(k4 * 4 + j) * 32];
#pragma unroll
            for (int c = 0; c < 32; c++) {
                asm("fma.rn.f32x2 %0, %1, %2, %0;"
                    : "+l"(acc[c])
                    : "l"(xx), "l"(wr[c]));
            }
        }
    }

    float s = g_dis[row];
    s = s * s;
    float2* hr = (float2*)(g_h + (size_t)row * 64);
    float2* orow = (float2*)(out + (size_t)row * 64);
#pragma unroll
    for (int c = 0; c < 32; c++) {
        float lo, hi;
        asm("mov.b64 {%0, %1}, %2;" : "=f"(lo), "=f"(hi) : "l"(acc[c]));
        hr[c] = make_float2(lo, hi);
        orow[c] = make_float2(lo * s, hi * s);
    }
}

// ---------------------------------------------------------------------------
// Scatter: out[col] += h[row] * norm.
// 512 edges staged per block; 16 lanes per edge (one float4 each);
// 2-edge software pipeline to keep 2 L2 loads in flight per group.
#define SC_EDGES 512
__global__ void __launch_bounds__(512) k_scatter(const void* __restrict__ ei,
                                                 const float* __restrict__ ew,
                                                 float* __restrict__ out,
                                                 int E, int n) {
    __shared__ int s_row[SC_EDGES];
    __shared__ int s_col[SC_EDGES];
    __shared__ float s_nrm[SC_EDGES];

    int e = blockIdx.x * SC_EDGES + threadIdx.x;
    int is64 = g_is64;
    if (e < E) {
        int r = load_idx(ei, is64, (size_t)e);
        int c = load_idx(ei, is64, (size_t)E + e);
        if ((unsigned)r < (unsigned)n && (unsigned)c < (unsigned)n) {
            s_row[threadIdx.x] = r;
            s_col[threadIdx.x] = c;
            s_nrm[threadIdx.x] = g_dis[r] * __ldg(&ew[e]) * g_dis[c];
        } else {
            s_row[threadIdx.x] = 0;
            s_col[threadIdx.x] = -1;
            s_nrm[threadIdx.x] = 0.0f;
        }
    } else {
        s_row[threadIdx.x] = 0;
        s_col[threadIdx.x] = -1;
        s_nrm[threadIdx.x] = 0.0f;
    }
    __syncthreads();

    const int sub = threadIdx.x & 15;   // lane within 16-lane edge group
    const int grp = threadIdx.x >> 4;   // 32 groups per block
    const int NIT = SC_EDGES / 32;      // 16 edges per group

    // Software pipeline: load edge i+1's h-row before RED of edge i.
    int le = grp;
    int c0 = s_col[le];
    int r0 = s_row[le];
    float n0 = s_nrm[le];
    float4 v0 = make_float4(0.f, 0.f, 0.f, 0.f);
    if (c0 >= 0)
        v0 = *(const float4*)(g_h + (size_t)r0 * 64 + sub * 4);

#pragma unroll 4
    for (int it = 1; it <= NIT; it++) {
        int c1 = -1, r1 = 0;
        float n1 = 0.f;
        float4 v1 = make_float4(0.f, 0.f, 0.f, 0.f);
        if (it < NIT) {
            int nle = grp + it * 32;
            c1 = s_col[nle];
            r1 = s_row[nle];
            n1 = s_nrm[nle];
            if (c1 >= 0)
                v1 = *(const float4*)(g_h + (size_t)r1 * 64 + sub * 4);
        }
        if (c0 >= 0) {
            float* dst = out + (size_t)c0 * 64 + sub * 4;
            asm volatile("red.global.add.v4.f32 [%0], {%1, %2, %3, %4};"
                         :: "l"(dst), "f"(v0.x * n0), "f"(v0.y * n0),
                            "f"(v0.z * n0), "f"(v0.w * n0)
                         : "memory");
        }
        c0 = c1; r0 = r1; n0 = n1; v0 = v1;
    }
}

// ---------------------------------------------------------------------------
// Epilogue: out = sigmoid(out + b), vectorized float4 (64 floats/row = 16 vec4).
__global__ void k_final(float* __restrict__ out, const float* __restrict__ b,
                        int total4) {
    int i = blockIdx.x * blockDim.x + threadIdx.x;
    if (i < total4) {
        float4 v = ((const float4*)out)[i];
        int bb = (i & 15) * 4;               // column of first element
        v.x = 1.0f / (1.0f + __expf(-(v.x + b[bb + 0])));
        v.y = 1.0f / (1.0f + __expf(-(v.y + b[bb + 1])));
        v.z = 1.0f / (1.0f + __expf(-(v.z + b[bb + 2])));
        v.w = 1.0f / (1.0f + __expf(-(v.w + b[bb + 3])));
        ((float4*)out)[i] = v;
    }
}

// ---------------------------------------------------------------------------
extern "C" void kernel_launch(void* const* d_in, const int* in_sizes, int n_in,
                              void* d_out, int out_size) {
    const float* x  = (const float*)d_in[0];
    const void*  ei = d_in[1];
    const float* ew = (const float*)d_in[2];
    const float* W  = (const float*)d_in[3];
    const float* b  = (const float*)d_in[4];
    float* out = (float*)d_out;

    int n = in_sizes[0] / 128;   // 100000
    int E = in_sizes[2];         // 3200000
    if (n > NMAX) return;

    int nb_n = (n + 255) / 256;

    k_detect<<<1, 256>>>((const int*)ei, E);
    k_deg_init<<<nb_n, 256>>>(n);
    k_deg_acc<<<(E + 255) / 256, 256>>>(ei, ew, E, n);
    k_dis<<<nb_n, 256>>>(n);
    k_gemm<<<nb_n, 256>>>(x, W, out, n);
    k_scatter<<<(E + SC_EDGES - 1) / SC_EDGES, SC_EDGES>>>(ei, ew, out, E, n);
    k_final<<<(n * 16 + 255) / 256, 256>>>(out, b, n * 16);
}

// round 6
// speedup vs baseline: 1.1848x; 1.1848x over previous
#include <cuda_runtime.h>

// ============================================================================
// GCNConv: out = sigmoid( scatter_add( (x@W)[row] * norm, col ) + b )
// norm = dis[row]*w*dis[col], dis = rsqrt(deg), deg = seg_sum(w,col) + 1
//
// Strategy: CSR-bin edges by target col (hist + scan + binfill), then each
// 16-lane group OWNS one output node: register accumulation, zero atomics on
// the feature data, out written exactly once (self-loop + bias + sigmoid fused).
// ============================================================================

#define NMAX 100000
#define EMAX 3400000

__device__ float g_deg[NMAX];
__device__ float g_dis[NMAX];
__device__ int   g_cnt[NMAX];
__device__ int   g_off[NMAX];     // scan scratch -> exclusive offsets
__device__ int   g_ptr[NMAX];     // binfill write cursors
__device__ int   g_bsum[512];
__device__ int   g_boff[512];
__device__ float g_h[(size_t)NMAX * 64];
__device__ int2  g_edge[EMAX];    // {src row, norm as bits}, grouped by col
__device__ int   g_is64;

// ---------------------------------------------------------------------------
// Detect edge_index dtype: int64 LE with values < 2^31 has all odd words 0.
__global__ void k_detect(const int* __restrict__ ei32, int E) {
    __shared__ int nz;
    if (threadIdx.x == 0) nz = 0;
    __syncthreads();
    int idx = 2 * threadIdx.x + 1;
    if (idx < 2 * E && ei32[idx] != 0) atomicOr(&nz, 1);
    __syncthreads();
    if (threadIdx.x == 0) g_is64 = (nz == 0) ? 1 : 0;
}

__device__ __forceinline__ int load_idx(const void* ei, int is64, size_t pos) {
    if (is64) return (int)((const long long*)ei)[pos];
    return ((const int*)ei)[pos];
}

// ---------------------------------------------------------------------------
__global__ void k_init(int n) {
    int i = blockIdx.x * blockDim.x + threadIdx.x;
    if (i < n) { g_deg[i] = 1.0f; g_cnt[i] = 0; }   // self-loop weight 1
}

// deg[col] += w ; cnt[col] += 1
__global__ void k_deg_acc(const void* __restrict__ ei,
                          const float* __restrict__ ew, int E, int n) {
    int e = blockIdx.x * blockDim.x + threadIdx.x;
    if (e < E) {
        int is64 = g_is64;
        int c = load_idx(ei, is64, (size_t)E + e);
        if ((unsigned)c < (unsigned)n) {
            atomicAdd(&g_deg[c], __ldg(&ew[e]));
            atomicAdd(&g_cnt[c], 1);
        }
    }
}

// ---------------------------------------------------------------------------
// GEMM: h = x @ W (packed f32x2 FMA, W in smem). Epilogue: store h and dis.
__global__ void __launch_bounds__(256) k_gemm(const float* __restrict__ x,
                                              const float* __restrict__ W,
                                              int n) {
    __shared__ unsigned long long w2[128 * 32];
    const unsigned long long* Wp = (const unsigned long long*)W;
    for (int i = threadIdx.x; i < 128 * 32; i += blockDim.x) w2[i] = Wp[i];
    __syncthreads();

    int row = blockIdx.x * blockDim.x + threadIdx.x;
    if (row >= n) return;

    unsigned long long acc[32];
#pragma unroll
    for (int c = 0; c < 32; c++) acc[c] = 0ull;

    const float4* xr = (const float4*)(x + (size_t)row * 128);
#pragma unroll 2
    for (int k4 = 0; k4 < 32; k4++) {
        float4 xv = xr[k4];
        float xs[4] = {xv.x, xv.y, xv.z, xv.w};
#pragma unroll
        for (int j = 0; j < 4; j++) {
            unsigned long long xx;
            asm("mov.b64 %0, {%1, %1};" : "=l"(xx) : "f"(xs[j]));
            const unsigned long long* wr = &w2[(k4 * 4 + j) * 32];
#pragma unroll
            for (int c = 0; c < 32; c++) {
                asm("fma.rn.f32x2 %0, %1, %2, %0;"
                    : "+l"(acc[c])
                    : "l"(xx), "l"(wr[c]));
            }
        }
    }

    float d = g_deg[row];
    g_dis[row] = (d > 0.0f) ? rsqrtf(d) : 0.0f;

    float2* hr = (float2*)(g_h + (size_t)row * 64);
#pragma unroll
    for (int c = 0; c < 32; c++) {
        float lo, hi;
        asm("mov.b64 {%0, %1}, %2;" : "=f"(lo), "=f"(hi) : "l"(acc[c]));
        hr[c] = make_float2(lo, hi);
    }
}

// ---------------------------------------------------------------------------
// Scan of g_cnt -> exclusive offsets g_off (+ cursors g_ptr). 3 kernels.
__global__ void k_scan1(int n) {
    __shared__ int sh[256];
    int i = blockIdx.x * 256 + threadIdx.x;
    int v = (i < n) ? g_cnt[i] : 0;
    sh[threadIdx.x] = v;
    __syncthreads();
#pragma unroll
    for (int d = 1; d < 256; d <<= 1) {
        int t = (threadIdx.x >= d) ? sh[threadIdx.x - d] : 0;
        __syncthreads();
        sh[threadIdx.x] += t;
        __syncthreads();
    }
    if (i < n) g_off[i] = sh[threadIdx.x];          // inclusive within block
    if (threadIdx.x == 255) g_bsum[blockIdx.x] = sh[255];
}

__global__ void k_scan2(int nb) {
    __shared__ int sh[512];
    int v = (threadIdx.x < nb) ? g_bsum[threadIdx.x] : 0;
    sh[threadIdx.x] = v;
    __syncthreads();
#pragma unroll
    for (int d = 1; d < 512; d <<= 1) {
        int t = (threadIdx.x >= d) ? sh[threadIdx.x - d] : 0;
        __syncthreads();
        sh[threadIdx.x] += t;
        __syncthreads();
    }
    if (threadIdx.x < nb) g_boff[threadIdx.x] = sh[threadIdx.x] - v;  // exclusive
}

__global__ void k_scan3(int n) {
    int i = blockIdx.x * 256 + threadIdx.x;
    if (i < n) {
        int excl = g_off[i] + g_boff[blockIdx.x] - g_cnt[i];
        g_off[i] = excl;
        g_ptr[i] = excl;
    }
}

// ---------------------------------------------------------------------------
// Bin edges by col: g_edge[pos] = {row, norm}
__global__ void k_binfill(const void* __restrict__ ei,
                          const float* __restrict__ ew, int E, int n) {
    int e = blockIdx.x * blockDim.x + threadIdx.x;
    if (e >= E) return;
    int is64 = g_is64;
    int r = load_idx(ei, is64, (size_t)e);
    int c = load_idx(ei, is64, (size_t)E + e);
    if ((unsigned)r >= (unsigned)n || (unsigned)c >= (unsigned)n) return;
    float nrm = g_dis[r] * __ldg(&ew[e]) * g_dis[c];
    int pos = atomicAdd(&g_ptr[c], 1);
    if (pos < EMAX) g_edge[pos] = make_int2(r, __float_as_int(nrm));
}

// ---------------------------------------------------------------------------
// Gather: each 16-lane group owns node c. acc = sum_e h[row_e]*nrm_e (+self),
// out[c] = sigmoid(acc + b). Register accumulation, single store, no atomics.
// Depth-2 software pipeline: edge meta 3 ahead, h-rows 2 ahead (MLP=2/group).
__global__ void __launch_bounds__(256) k_gather(float* __restrict__ out,
                                                const float* __restrict__ b,
                                                int n) {
    int c = (blockIdx.x * 256 + threadIdx.x) >> 4;
    int sub = threadIdx.x & 15;
    if (c >= n) return;

    int start = g_off[c];
    int len = g_cnt[c];

    float4 acc = make_float4(0.f, 0.f, 0.f, 0.f);

    int2 e0 = make_int2(0, 0), e1 = make_int2(0, 0), e2 = make_int2(0, 0);
    float4 v0 = make_float4(0.f, 0.f, 0.f, 0.f);
    float4 v1 = make_float4(0.f, 0.f, 0.f, 0.f);
    if (len > 0) e0 = g_edge[start];
    if (len > 1) e1 = g_edge[start + 1];
    if (len > 2) e2 = g_edge[start + 2];
    if (len > 0) v0 = *(const float4*)(g_h + (size_t)e0.x * 64 + sub * 4);
    if (len > 1) v1 = *(const float4*)(g_h + (size_t)e1.x * 64 + sub * 4);

    for (int i = 0; i < len; i++) {
        int2 e3 = (i + 3 < len) ? g_edge[start + i + 3] : make_int2(0, 0);
        float4 v2 = make_float4(0.f, 0.f, 0.f, 0.f);
        if (i + 2 < len)
            v2 = *(const float4*)(g_h + (size_t)e2.x * 64 + sub * 4);
        float nm = __int_as_float(e0.y);
        acc.x += v0.x * nm;
        acc.y += v0.y * nm;
        acc.z += v0.z * nm;
        acc.w += v0.w * nm;
        e0 = e1; e1 = e2; e2 = e3;
        v0 = v1; v1 = v2;
    }

    // Self-loop: + h[c] * dis[c]^2
    float s = g_dis[c];
    float ss = s * s;
    float4 hv = *(const float4*)(g_h + (size_t)c * 64 + sub * 4);
    acc.x += hv.x * ss;
    acc.y += hv.y * ss;
    acc.z += hv.z * ss;
    acc.w += hv.w * ss;

    // Bias + sigmoid, single vectorized store.
    float4 bv = *(const float4*)(b + sub * 4);
    float4 o;
    o.x = 1.0f / (1.0f + __expf(-(acc.x + bv.x)));
    o.y = 1.0f / (1.0f + __expf(-(acc.y + bv.y)));
    o.z = 1.0f / (1.0f + __expf(-(acc.z + bv.z)));
    o.w = 1.0f / (1.0f + __expf(-(acc.w + bv.w)));
    *(float4*)(out + (size_t)c * 64 + sub * 4) = o;
}

// ---------------------------------------------------------------------------
extern "C" void kernel_launch(void* const* d_in, const int* in_sizes, int n_in,
                              void* d_out, int out_size) {
    const float* x  = (const float*)d_in[0];
    const void*  ei = d_in[1];
    const float* ew = (const float*)d_in[2];
    const float* W  = (const float*)d_in[3];
    const float* b  = (const float*)d_in[4];
    float* out = (float*)d_out;

    int n = in_sizes[0] / 128;   // 100000
    int E = in_sizes[2];         // 3200000
    if (n > NMAX || E > EMAX) return;

    int nb_n = (n + 255) / 256;
    int nb_e = (E + 255) / 256;

    k_detect<<<1, 256>>>((const int*)ei, E);          // 0
    k_init<<<nb_n, 256>>>(n);                         // 1
    k_deg_acc<<<nb_e, 256>>>(ei, ew, E, n);           // 2
    k_gemm<<<nb_n, 256>>>(x, W, n);                   // 3  <- profiled slot
    k_scan1<<<nb_n, 256>>>(n);                        // 4
    k_scan2<<<1, 512>>>(nb_n);                        // 5
    k_scan3<<<nb_n, 256>>>(n);                        // 6
    k_binfill<<<nb_e, 256>>>(ei, ew, E, n);           // 7
    k_gather<<<(n * 16 + 255) / 256, 256>>>(out, b, n); // 8
}

// round 8
// speedup vs baseline: 1.2868x; 1.0861x over previous
#include <cuda_runtime.h>

// ============================================================================
// GCNConv: out = sigmoid( scatter_add( (x@W)[row] * norm, col ) + b )
// norm = dis[row]*w*dis[col], dis = rsqrt(deg), deg = seg_sum(w,col) + 1
//
// CSR-bin edges by target col (hist + scan + binfill); each 16-lane group
// OWNS one output node (register accumulation, no feature atomics, fused
// self-loop + bias + sigmoid).
// GEMM: 2 rows x 32 cols per thread, LDS.128 W operands, XOR bank swizzle
// -> 4 FMA2 per LDS (was 1:1, smem-crossbar bound at L1=74.6%).
// ============================================================================

#define NMAX 100000
#define EMAX 3400000

typedef unsigned long long ull;

__device__ float g_deg[NMAX];
__device__ float g_dis[NMAX];
__device__ int   g_cnt[NMAX];
__device__ int   g_off[NMAX];
__device__ int   g_ptr[NMAX];
__device__ int   g_bsum[512];
__device__ int   g_boff[512];
__device__ float g_h[(size_t)NMAX * 64];
__device__ int2  g_edge[EMAX];
__device__ int   g_is64;

// ---------------------------------------------------------------------------
__global__ void k_detect(const int* __restrict__ ei32, int E) {
    __shared__ int nz;
    if (threadIdx.x == 0) nz = 0;
    __syncthreads();
    int idx = 2 * threadIdx.x + 1;
    if (idx < 2 * E && ei32[idx] != 0) atomicOr(&nz, 1);
    __syncthreads();
    if (threadIdx.x == 0) g_is64 = (nz == 0) ? 1 : 0;
}

__device__ __forceinline__ int load_idx(const void* ei, int is64, size_t pos) {
    if (is64) return (int)((const long long*)ei)[pos];
    return ((const int*)ei)[pos];
}

// ---------------------------------------------------------------------------
__global__ void k_init(int n) {
    int i = blockIdx.x * blockDim.x + threadIdx.x;
    if (i < n) { g_deg[i] = 1.0f; g_cnt[i] = 0; }
}

__global__ void k_deg_acc(const void* __restrict__ ei,
                          const float* __restrict__ ew, int E, int n) {
    int e = blockIdx.x * blockDim.x + threadIdx.x;
    if (e < E) {
        int is64 = g_is64;
        int c = load_idx(ei, is64, (size_t)E + e);
        if ((unsigned)c < (unsigned)n) {
            atomicAdd(&g_deg[c], __ldg(&ew[e]));
            atomicAdd(&g_cnt[c], 1);
        }
    }
}

// ---------------------------------------------------------------------------
// GEMM: h = x @ W. Thread = (row-pair, col-half): 2 rows x 32 cols.
// W in smem as ulonglong2 (2 f32x2 per 16B), XOR-swizzled so the two
// col-halves occupy disjoint bank groups.
__global__ void __launch_bounds__(256) k_gemm(const float* __restrict__ x,
                                              const float* __restrict__ W,
                                              int n) {
    // Logical: per k (0..127), 16 units of 16B (unit u covers col-pairs 2u,2u+1).
    // Physical: phys = k*16 + (u & 8) + ((u & 7) ^ ((u & 8) >> 1)).
    __shared__ ulonglong2 w4[128 * 16];
    const ulonglong2* Wp = (const ulonglong2*)W;
    for (int i = threadIdx.x; i < 2048; i += 256) {
        int k = i >> 4, u = i & 15;
        int phys = (k << 4) + (u & 8) + ((u & 7) ^ ((u & 8) >> 1));
        w4[phys] = Wp[i];
    }
    __syncthreads();

    int t = blockIdx.x * 256 + threadIdx.x;
    int pair = t >> 1;
    int half = t & 1;
    int r0 = pair * 2;
    if (r0 >= n) return;
    int r1 = r0 + 1;
    bool has2 = (r1 < n);

    ull acc0[16], acc1[16];
#pragma unroll
    for (int i = 0; i < 16; i++) { acc0[i] = 0ull; acc1[i] = 0ull; }

    const int hx = half << 2;          // XOR key: 0 or 4
    const int ub = half << 3;          // unit base: 0 or 8
    // Hoisted swizzled unit offsets (k-invariant).
    int off[8];
#pragma unroll
    for (int q = 0; q < 8; q++) off[q] = ub + (q ^ hx);

    const float4* xa = (const float4*)(x + (size_t)r0 * 128);
    const float4* xb = (const float4*)(x + (size_t)(has2 ? r1 : r0) * 128);

    for (int k4 = 0; k4 < 32; k4++) {
        float4 av = xa[k4];
        float4 bv = xb[k4];
        float as_[4] = {av.x, av.y, av.z, av.w};
        float bs_[4] = {bv.x, bv.y, bv.z, bv.w};
#pragma unroll
        for (int j = 0; j < 4; j++) {
            ull ax, bx;
            asm("mov.b64 %0, {%1, %1};" : "=l"(ax) : "f"(as_[j]));
            asm("mov.b64 %0, {%1, %1};" : "=l"(bx) : "f"(bs_[j]));
            const ulonglong2* base = w4 + (((k4 << 2) + j) << 4);
#pragma unroll
            for (int q = 0; q < 8; q++) {
                ulonglong2 wv = base[off[q]];
                asm("fma.rn.f32x2 %0, %1, %2, %0;"
                    : "+l"(acc0[2 * q]) : "l"(ax), "l"(wv.x));
                asm("fma.rn.f32x2 %0, %1, %2, %0;"
                    : "+l"(acc0[2 * q + 1]) : "l"(ax), "l"(wv.y));
                asm("fma.rn.f32x2 %0, %1, %2, %0;"
                    : "+l"(acc1[2 * q]) : "l"(bx), "l"(wv.x));
                asm("fma.rn.f32x2 %0, %1, %2, %0;"
                    : "+l"(acc1[2 * q + 1]) : "l"(bx), "l"(wv.y));
            }
        }
    }

    if (half == 0) {
        float d0 = g_deg[r0];
        g_dis[r0] = (d0 > 0.0f) ? rsqrtf(d0) : 0.0f;
        if (has2) {
            float d1 = g_deg[r1];
            g_dis[r1] = (d1 > 0.0f) ? rsqrtf(d1) : 0.0f;
        }
    }

    ull* h0 = (ull*)(g_h + (size_t)r0 * 64) + half * 16;
#pragma unroll
    for (int i = 0; i < 16; i++) h0[i] = acc0[i];
    if (has2) {
        ull* h1 = (ull*)(g_h + (size_t)r1 * 64) + half * 16;
#pragma unroll
        for (int i = 0; i < 16; i++) h1[i] = acc1[i];
    }
}

// ---------------------------------------------------------------------------
// Scan of g_cnt -> exclusive offsets g_off (+ cursors g_ptr).
__global__ void k_scan1(int n) {
    __shared__ int sh[256];
    int i = blockIdx.x * 256 + threadIdx.x;
    int v = (i < n) ? g_cnt[i] : 0;
    sh[threadIdx.x] = v;
    __syncthreads();
#pragma unroll
    for (int d = 1; d < 256; d <<= 1) {
        int t = (threadIdx.x >= d) ? sh[threadIdx.x - d] : 0;
        __syncthreads();
        sh[threadIdx.x] += t;
        __syncthreads();
    }
    if (i < n) g_off[i] = sh[threadIdx.x];
    if (threadIdx.x == 255) g_bsum[blockIdx.x] = sh[255];
}

__global__ void k_scan2(int nb) {
    __shared__ int sh[512];
    int v = (threadIdx.x < nb) ? g_bsum[threadIdx.x] : 0;
    sh[threadIdx.x] = v;
    __syncthreads();
#pragma unroll
    for (int d = 1; d < 512; d <<= 1) {
        int t = (threadIdx.x >= d) ? sh[threadIdx.x - d] : 0;
        __syncthreads();
        sh[threadIdx.x] += t;
        __syncthreads();
    }
    if (threadIdx.x < nb) g_boff[threadIdx.x] = sh[threadIdx.x] - v;
}

__global__ void k_scan3(int n) {
    int i = blockIdx.x * 256 + threadIdx.x;
    if (i < n) {
        int excl = g_off[i] + g_boff[blockIdx.x] - g_cnt[i];
        g_off[i] = excl;
        g_ptr[i] = excl;
    }
}

// ---------------------------------------------------------------------------
__global__ void k_binfill(const void* __restrict__ ei,
                          const float* __restrict__ ew, int E, int n) {
    int e = blockIdx.x * blockDim.x + threadIdx.x;
    if (e >= E) return;
    int is64 = g_is64;
    int r = load_idx(ei, is64, (size_t)e);
    int c = load_idx(ei, is64, (size_t)E + e);
    if ((unsigned)r >= (unsigned)n || (unsigned)c >= (unsigned)n) return;
    float nrm = g_dis[r] * __ldg(&ew[e]) * g_dis[c];
    int pos = atomicAdd(&g_ptr[c], 1);
    if (pos < EMAX) g_edge[pos] = make_int2(r, __float_as_int(nrm));
}

// ---------------------------------------------------------------------------
// Gather: 16-lane group owns node c; depth-2 pipeline on h-row loads.
__global__ void __launch_bounds__(256) k_gather(float* __restrict__ out,
                                                const float* __restrict__ b,
                                                int n) {
    int c = (blockIdx.x * 256 + threadIdx.x) >> 4;
    int sub = threadIdx.x & 15;
    if (c >= n) return;

    int start = g_off[c];
    int len = g_cnt[c];

    float4 acc = make_float4(0.f, 0.f, 0.f, 0.f);

    int2 e0 = make_int2(0, 0), e1 = make_int2(0, 0), e2 = make_int2(0, 0);
    float4 v0 = make_float4(0.f, 0.f, 0.f, 0.f);
    float4 v1 = make_float4(0.f, 0.f, 0.f, 0.f);
    if (len > 0) e0 = g_edge[start];
    if (len > 1) e1 = g_edge[start + 1];
    if (len > 2) e2 = g_edge[start + 2];
    if (len > 0) v0 = *(const float4*)(g_h + (size_t)e0.x * 64 + sub * 4);
    if (len > 1) v1 = *(const float4*)(g_h + (size_t)e1.x * 64 + sub * 4);

    for (int i = 0; i < len; i++) {
        int2 e3 = (i + 3 < len) ? g_edge[start + i + 3] : make_int2(0, 0);
        float4 v2 = make_float4(0.f, 0.f, 0.f, 0.f);
        if (i + 2 < len)
            v2 = *(const float4*)(g_h + (size_t)e2.x * 64 + sub * 4);
        float nm = __int_as_float(e0.y);
        acc.x += v0.x * nm;
        acc.y += v0.y * nm;
        acc.z += v0.z * nm;
        acc.w += v0.w * nm;
        e0 = e1; e1 = e2; e2 = e3;
        v0 = v1; v1 = v2;
    }

    float s = g_dis[c];
    float ss = s * s;
    float4 hv = *(const float4*)(g_h + (size_t)c * 64 + sub * 4);
    acc.x += hv.x * ss;
    acc.y += hv.y * ss;
    acc.z += hv.z * ss;
    acc.w += hv.w * ss;

    float4 bv = *(const float4*)(b + sub * 4);
    float4 o;
    o.x = 1.0f / (1.0f + __expf(-(acc.x + bv.x)));
    o.y = 1.0f / (1.0f + __expf(-(acc.y + bv.y)));
    o.z = 1.0f / (1.0f + __expf(-(acc.z + bv.z)));
    o.w = 1.0f / (1.0f + __expf(-(acc.w + bv.w)));
    *(float4*)(out + (size_t)c * 64 + sub * 4) = o;
}

// ---------------------------------------------------------------------------
extern "C" void kernel_launch(void* const* d_in, const int* in_sizes, int n_in,
                              void* d_out, int out_size) {
    const float* x  = (const float*)d_in[0];
    const void*  ei = d_in[1];
    const float* ew = (const float*)d_in[2];
    const float* W  = (const float*)d_in[3];
    const float* b  = (const float*)d_in[4];
    float* out = (float*)d_out;

    int n = in_sizes[0] / 128;   // 100000
    int E = in_sizes[2];         // 3200000
    if (n > NMAX || E > EMAX) return;

    int nb_n = (n + 255) / 256;
    int nb_e = (E + 255) / 256;
    int nb_g = (n + 255) / 256;  // gemm: n threads total (2 halves per row-pair)

    k_detect<<<1, 256>>>((const int*)ei, E);            // 0
    k_init<<<nb_n, 256>>>(n);                           // 1
    k_deg_acc<<<nb_e, 256>>>(ei, ew, E, n);             // 2
    k_gemm<<<nb_g, 256>>>(x, W, n);                     // 3  <- profiled slot
    k_scan1<<<nb_n, 256>>>(n);                          // 4
    k_scan2<<<1, 512>>>(nb_n);                          // 5
    k_scan3<<<nb_n, 256>>>(n);                          // 6
    k_binfill<<<nb_e, 256>>>(ei, ew, E, n);             // 7
    k_gather<<<(n * 16 + 255) / 256, 256>>>(out, b, n); // 8
}